// round 13
// baseline (speedup 1.0000x reference)
#include <cuda_runtime.h>
#include <cuda_bf16.h>
#include <math.h>
#include <stdint.h>

#define NTOK 16384
#define DM   1024
#define DF   4096
#define NE   8

__device__ int   g_cnt[NE], g_off[NE], g_fill[NE], g_list[NTOK];
__device__ int   g_ok;
__device__ float g_h[(size_t)NTOK * DF];                 // fp32 H (fallback path)
__device__ __nv_bfloat16 gXh[(size_t)NTOK * DM];
__device__ __nv_bfloat16 gXl[(size_t)NTOK * DM];
__device__ __nv_bfloat16 gW1h[(size_t)NE * DF * DM];     // [e][n][k]
__device__ __nv_bfloat16 gW1l[(size_t)NE * DF * DM];
__device__ __nv_bfloat16 gW2h[(size_t)NE * DM * DF];     // [e][n][k]
__device__ __nv_bfloat16 gW2l[(size_t)NE * DM * DF];
__device__ __nv_bfloat16 gHh[(size_t)NTOK * DF];
__device__ __nv_bfloat16 gHl[(size_t)NTOK * DF];

__device__ __forceinline__ void mma16816(float* c, const uint32_t* a, const uint32_t* b) {
    asm volatile("mma.sync.aligned.m16n8k16.row.col.f32.bf16.bf16.f32 "
                 "{%0,%1,%2,%3},{%4,%5,%6,%7},{%8,%9},{%0,%1,%2,%3};"
                 : "+f"(c[0]), "+f"(c[1]), "+f"(c[2]), "+f"(c[3])
                 : "r"(a[0]), "r"(a[1]), "r"(a[2]), "r"(a[3]), "r"(b[0]), "r"(b[1]));
}
__device__ __forceinline__ void split2(float x0, float x1, uint32_t& hi, uint32_t& lo) {
    __nv_bfloat16 h0 = __float2bfloat16(x0), h1 = __float2bfloat16(x1);
    __nv_bfloat16 l0 = __float2bfloat16(x0 - __bfloat162float(h0));
    __nv_bfloat16 l1 = __float2bfloat16(x1 - __bfloat162float(h1));
    hi = (uint32_t)__bfloat16_as_ushort(h0) | ((uint32_t)__bfloat16_as_ushort(h1) << 16);
    lo = (uint32_t)__bfloat16_as_ushort(l0) | ((uint32_t)__bfloat16_as_ushort(l1) << 16);
}
__device__ __forceinline__ float gelu_tanh(float x) {
    float x3 = x * x * x;
    return 0.5f * x * (1.0f + tanhf(0.7978845608028654f * (x + 0.044715f * x3)));
}

// ------------------------------- routing ------------------------------------
__global__ void k_route0() { if (threadIdx.x < NE) { g_cnt[threadIdx.x] = 0; g_fill[threadIdx.x] = 0; } }
__global__ void k_route1(const int* __restrict__ idx) {
    int t = blockIdx.x * blockDim.x + threadIdx.x;
    if (t < NTOK) atomicAdd(&g_cnt[idx[t]], 1);
}
__global__ void k_route2() {
    if (threadIdx.x == 0) { int s = 0; for (int e = 0; e < NE; e++) { g_off[e] = s; s += g_cnt[e]; } }
}
__global__ void k_route3(const int* __restrict__ idx) {
    int t = blockIdx.x * blockDim.x + threadIdx.x;
    if (t < NTOK) { int e = idx[t]; int p = atomicAdd(&g_fill[e], 1); g_list[g_off[e] + p] = t; }
}

// ---- probe: validates HMMA + fragment maps + conversion on real data ----
__global__ void k_probe(const float* __restrict__ X, const float* __restrict__ W1) {
    int lane = threadIdx.x & 31;
    int g = lane >> 2, tg = lane & 3;
    uint32_t ah[4], al[4], bh[2], bl[2];
    split2(X[(size_t)g * DM + 2 * tg],            X[(size_t)g * DM + 2 * tg + 1],       ah[0], al[0]);
    split2(X[(size_t)(g + 8) * DM + 2 * tg],      X[(size_t)(g + 8) * DM + 2 * tg + 1], ah[1], al[1]);
    split2(X[(size_t)g * DM + 2 * tg + 8],        X[(size_t)g * DM + 2 * tg + 9],       ah[2], al[2]);
    split2(X[(size_t)(g + 8) * DM + 2 * tg + 8],  X[(size_t)(g + 8) * DM + 2 * tg + 9], ah[3], al[3]);
    split2(W1[(size_t)(2 * tg) * DF + g],     W1[(size_t)(2 * tg + 1) * DF + g], bh[0], bl[0]);
    split2(W1[(size_t)(2 * tg + 8) * DF + g], W1[(size_t)(2 * tg + 9) * DF + g], bh[1], bl[1]);
    float c[4] = {0.f, 0.f, 0.f, 0.f};
    mma16816(c, ah, bh);
    mma16816(c, ah, bl);
    mma16816(c, al, bh);
    float r0 = 0.f, r1 = 0.f, r2 = 0.f, r3 = 0.f;
    for (int k = 0; k < 16; k++) {
        float w0 = W1[(size_t)k * DF + 2 * tg], w1 = W1[(size_t)k * DF + 2 * tg + 1];
        float xa = X[(size_t)g * DM + k], xb = X[(size_t)(g + 8) * DM + k];
        r0 += xa * w0; r1 += xa * w1; r2 += xb * w0; r3 += xb * w1;
    }
    float err = fmaxf(fmaxf(fabsf(c[0] - r0), fabsf(c[1] - r1)),
                      fmaxf(fabsf(c[2] - r2), fabsf(c[3] - r3)));
    float mag = fabsf(r0) + fabsf(r1) + fabsf(r2) + fabsf(r3);
    unsigned okm = __ballot_sync(0xffffffffu, err < 5e-3f);
    unsigned nzm = __ballot_sync(0xffffffffu, mag > 1e-3f);
    if (lane == 0) g_ok = (okm == 0xffffffffu && nzm != 0u) ? 1 : 0;
}

// ------------------------------- converts -----------------------------------
__global__ __launch_bounds__(256) void k_convX(const float* __restrict__ X) {
    size_t i = (size_t)blockIdx.x * 256 + threadIdx.x;
    float4 v = ((const float4*)X)[i];
    uint32_t h0, l0, h1, l1;
    split2(v.x, v.y, h0, l0); split2(v.z, v.w, h1, l1);
    ((uint2*)gXh)[i] = make_uint2(h0, h1);
    ((uint2*)gXl)[i] = make_uint2(l0, l1);
}
// W [e][K][N] fp32 -> [e][N][K] bf16 hi/lo
__global__ __launch_bounds__(256) void k_convW(const float* __restrict__ W,
                                               __nv_bfloat16* __restrict__ outH,
                                               __nv_bfloat16* __restrict__ outL,
                                               int K, int N) {
    __shared__ float ts[64][65];
    int tid = threadIdx.x;
    int e = blockIdx.z, k0 = blockIdx.x * 64, n0 = blockIdx.y * 64;
    const float* Wp = W + (size_t)e * K * N;
    int kr = tid >> 2, ng = (tid & 3) * 16;
    #pragma unroll
    for (int it = 0; it < 4; it++) {
        int n = ng + it * 4;
        float4 v = *(const float4*)(Wp + (size_t)(k0 + kr) * N + n0 + n);
        ts[kr][n] = v.x; ts[kr][n + 1] = v.y; ts[kr][n + 2] = v.z; ts[kr][n + 3] = v.w;
    }
    __syncthreads();
    int kq = (tid & 15) * 4, nb = (tid >> 4) * 4;
    #pragma unroll
    for (int it = 0; it < 4; it++) {
        int nr = nb + it;
        uint32_t h0, l0, h1, l1;
        split2(ts[kq][nr], ts[kq + 1][nr], h0, l0);
        split2(ts[kq + 2][nr], ts[kq + 3][nr], h1, l1);
        size_t o = ((size_t)e * N + n0 + nr) * K + k0 + kq;
        *(uint2*)(outH + o) = make_uint2(h0, h1);
        *(uint2*)(outL + o) = make_uint2(l0, l1);
    }
}

// ================== FAST PATH: HMMA hi/lo grouped GEMM =======================
// BM=BN=128, BK=32. 40KB static SMEM (word stride 20/row), register dbl-buffer.
// SMEM word offsets: Ah@0, Al@2560, Bh@5120, Bl@7680.
template <int MODE>   // 0: X@W1 -> gelu -> H(split). 1: H@W2 -> +b2 -> scatter
__global__ __launch_bounds__(256, 1) void k_mma(const float* __restrict__ bias,
                                                float* __restrict__ out) {
    if (!g_ok) return;
    __shared__ uint32_t sm4[10240];
    const int tid = threadIdx.x, wid = tid >> 5, lane = tid & 31;
    const int e = blockIdx.z, lin = blockIdx.x;
    int mi, ni;
    if (MODE == 0) { mi = ((lin >> 9) << 4) | (lin & 15); ni = (lin & 511) >> 4; }
    else           { mi = ((lin >> 7) << 4) | (lin & 15); ni = (lin & 127) >> 4; }
    const int cnt = g_cnt[e], m0 = mi * 128;
    if (m0 >= cnt) return;
    const int off = g_off[e], n0 = ni * 128;
    const int K = MODE ? DF : DM;
    const int nk = K / 32;

    // ---- loader map: thread -> row r (0..127), 32B segment s (0..1) ----
    const int r = tid >> 1, s = tid & 1;
    const bool v = (m0 + r) < cnt;
    const char *aH, *aL, *bH, *bL;
    if (MODE == 0) {
        size_t ar = v ? (size_t)g_list[off + m0 + r] * DM * 2 : 0;
        aH = (const char*)gXh + ar;  aL = (const char*)gXl + ar;
        size_t br = ((size_t)e * DF + n0 + r) * (size_t)DM * 2;
        bH = (const char*)gW1h + br; bL = (const char*)gW1l + br;
    } else {
        size_t ar = (size_t)(off + m0 + (v ? r : 0)) * DF * 2;
        aH = (const char*)gHh + ar;  aL = (const char*)gHl + ar;
        size_t br = ((size_t)e * DM + n0 + r) * (size_t)DF * 2;
        bH = (const char*)gW2h + br; bL = (const char*)gW2l + br;
    }

    const int wm = wid & 1, wn = wid >> 1;
    const int g = lane >> 2, tg = lane & 3;

    float acc[4][4][4];
    #pragma unroll
    for (int i = 0; i < 4; i++)
        #pragma unroll
        for (int j = 0; j < 4; j++)
            #pragma unroll
            for (int q = 0; q < 4; q++) acc[i][j][q] = 0.f;

    uint4 rA[4], rB[4];   // {Ah0,Ah1,Al0,Al1}, {Bh0,Bh1,Bl0,Bl1}
    const uint4 z4 = make_uint4(0, 0, 0, 0);

    auto gload = [&](int c) {
        const size_t o = (size_t)c * 64 + (size_t)s * 32;
        if (v) {
            rA[0] = *(const uint4*)(aH + o); rA[1] = *(const uint4*)(aH + o + 16);
            rA[2] = *(const uint4*)(aL + o); rA[3] = *(const uint4*)(aL + o + 16);
        } else { rA[0] = z4; rA[1] = z4; rA[2] = z4; rA[3] = z4; }
        rB[0] = *(const uint4*)(bH + o); rB[1] = *(const uint4*)(bH + o + 16);
        rB[2] = *(const uint4*)(bL + o); rB[3] = *(const uint4*)(bL + o + 16);
    };
    auto sstore = [&]() {
        const int d = r * 20 + s * 8;
        *(uint4*)&sm4[d]            = rA[0]; *(uint4*)&sm4[d + 4]        = rA[1];
        *(uint4*)&sm4[2560 + d]     = rA[2]; *(uint4*)&sm4[2560 + d + 4] = rA[3];
        *(uint4*)&sm4[5120 + d]     = rB[0]; *(uint4*)&sm4[5120 + d + 4] = rB[1];
        *(uint4*)&sm4[7680 + d]     = rB[2]; *(uint4*)&sm4[7680 + d + 4] = rB[3];
    };

    gload(0); sstore();
    __syncthreads();

    for (int c = 0; c < nk; c++) {
        const bool more = (c + 1 < nk);
        if (more) gload(c + 1);
        #pragma unroll
        for (int kk = 0; kk < 2; kk++) {
            const int ko = kk * 8;
            uint32_t Bh[4][2], Bl[4][2];
            #pragma unroll
            for (int j = 0; j < 4; j++) {
                const int nb = 5120 + (wn * 32 + j * 8 + g) * 20 + tg + ko;
                Bh[j][0] = sm4[nb];        Bh[j][1] = sm4[nb + 4];
                Bl[j][0] = sm4[nb + 2560]; Bl[j][1] = sm4[nb + 2564];
            }
            #pragma unroll
            for (int i = 0; i < 4; i++) {
                const int ab = (wm * 64 + i * 16 + g) * 20 + tg + ko;
                uint32_t ah[4] = { sm4[ab], sm4[ab + 160], sm4[ab + 4], sm4[ab + 164] };
                uint32_t al[4] = { sm4[ab + 2560], sm4[ab + 2720], sm4[ab + 2564], sm4[ab + 2724] };
                #pragma unroll
                for (int j = 0; j < 4; j++) {
                    mma16816(acc[i][j], ah, Bh[j]);
                    mma16816(acc[i][j], ah, Bl[j]);
                    mma16816(acc[i][j], al, Bh[j]);
                }
            }
        }
        __syncthreads();
        if (more) sstore();
        __syncthreads();
    }

    const float* be = bias + (size_t)e * (MODE ? DM : DF);
    #pragma unroll
    for (int i = 0; i < 4; i++) {
        #pragma unroll
        for (int j = 0; j < 4; j++) {
            const int n  = n0 + wn * 32 + j * 8 + tg * 2;
            const int mL = m0 + wm * 64 + i * 16 + g;
            const int mH = mL + 8;
            const float bx = be[n], by = be[n + 1];
            if (MODE == 0) {
                if (mL < cnt) {
                    uint32_t hh, ll;
                    split2(gelu_tanh(acc[i][j][0] + bx), gelu_tanh(acc[i][j][1] + by), hh, ll);
                    size_t o = (size_t)(off + mL) * DF + n;
                    *(uint32_t*)(gHh + o) = hh; *(uint32_t*)(gHl + o) = ll;
                }
                if (mH < cnt) {
                    uint32_t hh, ll;
                    split2(gelu_tanh(acc[i][j][2] + bx), gelu_tanh(acc[i][j][3] + by), hh, ll);
                    size_t o = (size_t)(off + mH) * DF + n;
                    *(uint32_t*)(gHh + o) = hh; *(uint32_t*)(gHl + o) = ll;
                }
            } else {
                if (mL < cnt) {
                    float2 vv = make_float2(acc[i][j][0] + bx, acc[i][j][1] + by);
                    *(float2*)(out + (size_t)g_list[off + mL] * DM + n) = vv;
                }
                if (mH < cnt) {
                    float2 vv = make_float2(acc[i][j][2] + bx, acc[i][j][3] + by);
                    *(float2*)(out + (size_t)g_list[off + mH] * DM + n) = vv;
                }
            }
        }
    }
}

// ---- end-to-end checker: 8 sampled outputs recomputed in fp32; bad -> g_ok=0 ----
__global__ __launch_bounds__(256) void k_check(const float* __restrict__ X,
                                               const int* __restrict__ idx,
                                               const float* __restrict__ W1,
                                               const float* __restrict__ b1,
                                               const float* __restrict__ W2,
                                               const float* __restrict__ b2,
                                               const float* __restrict__ out) {
    if (!g_ok) return;
    __shared__ float red[256];
    int tid = threadIdx.x, sA = blockIdx.x;
    int t = sA * 2048 + 7;
    int n = (sA * 131 + 9) & (DM - 1);
    int e = idx[t];
    const float* xr = X + (size_t)t * DM;
    const float* w1 = W1 + (size_t)e * DM * DF;
    const float* w2 = W2 + (size_t)e * DF * DM;
    int f0 = tid * 16;
    float hs[16];
    #pragma unroll
    for (int u = 0; u < 16; u++) hs[u] = b1[(size_t)e * DF + f0 + u];
    for (int k = 0; k < DM; k++) {
        float xk = xr[k];
        const float* wr = w1 + (size_t)k * DF + f0;
        #pragma unroll
        for (int u = 0; u < 16; u++) hs[u] += xk * wr[u];
    }
    float accs = 0.f;
    #pragma unroll
    for (int u = 0; u < 16; u++) accs += gelu_tanh(hs[u]) * w2[(size_t)(f0 + u) * DM + n];
    red[tid] = accs;
    __syncthreads();
    for (int st = 128; st > 0; st >>= 1) { if (tid < st) red[tid] += red[tid + st]; __syncthreads(); }
    if (tid == 0) {
        float ref = red[0] + b2[(size_t)e * DM + n];
        float got = out[(size_t)t * DM + n];
        if (fabsf(got - ref) > 0.05f + 0.02f * fabsf(ref)) g_ok = 0;
    }
}

// =================== FALLBACK: proven FFMA GEMMs (6.9ms) =====================
__global__ __launch_bounds__(256, 2) void k_gemm1(
    const float* __restrict__ X, const float* __restrict__ W1,
    const float* __restrict__ b1)
{
    if (g_ok) return;
    int e = blockIdx.z, cnt = g_cnt[e], m0 = blockIdx.x * 128;
    if (m0 >= cnt) return;
    int off = g_off[e], n0 = blockIdx.y * 128;
    const float* B = W1 + (size_t)e * DM * DF;
    __shared__ float As[8][128];
    __shared__ float Bs[8][128];
    int tid = threadIdx.x, tx = tid & 15, ty = tid >> 4;
    int am = tid >> 1, akq = (tid & 1) * 4, mg = m0 + am;
    const float* arow = (mg < cnt) ? (X + (size_t)g_list[off + mg] * DM) : nullptr;
    int bk = tid >> 5, bn = (tid & 31) * 4;
    float acc[8][8];
    #pragma unroll
    for (int i = 0; i < 8; i++)
        #pragma unroll
        for (int j = 0; j < 8; j++) acc[i][j] = 0.f;
    for (int k0 = 0; k0 < DM; k0 += 8) {
        float4 av = make_float4(0.f, 0.f, 0.f, 0.f);
        if (arow) av = *(const float4*)(arow + k0 + akq);
        float4 bv = *(const float4*)(B + (size_t)(k0 + bk) * DF + n0 + bn);
        As[akq + 0][am] = av.x; As[akq + 1][am] = av.y;
        As[akq + 2][am] = av.z; As[akq + 3][am] = av.w;
        *(float4*)&Bs[bk][bn] = bv;
        __syncthreads();
        #pragma unroll
        for (int kk = 0; kk < 8; kk++) {
            float a[8], b[8];
            #pragma unroll
            for (int i = 0; i < 8; i++) a[i] = As[kk][ty * 8 + i];
            #pragma unroll
            for (int j = 0; j < 8; j++) b[j] = Bs[kk][tx * 8 + j];
            #pragma unroll
            for (int i = 0; i < 8; i++)
                #pragma unroll
                for (int j = 0; j < 8; j++) acc[i][j] += a[i] * b[j];
        }
        __syncthreads();
    }
    const float* bb = b1 + (size_t)e * DF + n0 + tx * 8;
    float4 b1lo = *(const float4*)(bb);
    float4 b1hi = *(const float4*)(bb + 4);
    #pragma unroll
    for (int i = 0; i < 8; i++) {
        int m = m0 + ty * 8 + i;
        if (m < cnt) {
            float* hrow = g_h + (size_t)(off + m) * DF + n0 + tx * 8;
            float4 v0, v1;
            v0.x = gelu_tanh(acc[i][0] + b1lo.x); v0.y = gelu_tanh(acc[i][1] + b1lo.y);
            v0.z = gelu_tanh(acc[i][2] + b1lo.z); v0.w = gelu_tanh(acc[i][3] + b1lo.w);
            v1.x = gelu_tanh(acc[i][4] + b1hi.x); v1.y = gelu_tanh(acc[i][5] + b1hi.y);
            v1.z = gelu_tanh(acc[i][6] + b1hi.z); v1.w = gelu_tanh(acc[i][7] + b1hi.w);
            *(float4*)(hrow) = v0; *(float4*)(hrow + 4) = v1;
        }
    }
}

__global__ __launch_bounds__(256, 2) void k_gemm2(
    const float* __restrict__ W2, const float* __restrict__ b2,
    float* __restrict__ out)
{
    if (g_ok) return;
    int e = blockIdx.z, cnt = g_cnt[e], m0 = blockIdx.x * 128;
    if (m0 >= cnt) return;
    int off = g_off[e], n0 = blockIdx.y * 128;
    const float* B = W2 + (size_t)e * DF * DM;
    __shared__ float As[8][128];
    __shared__ float Bs[8][128];
    int tid = threadIdx.x, tx = tid & 15, ty = tid >> 4;
    int am = tid >> 1, akq = (tid & 1) * 4, mg = m0 + am;
    const float* arow = (mg < cnt) ? (g_h + (size_t)(off + mg) * DF) : nullptr;
    int bk = tid >> 5, bn = (tid & 31) * 4;
    float acc[8][8];
    #pragma unroll
    for (int i = 0; i < 8; i++)
        #pragma unroll
        for (int j = 0; j < 8; j++) acc[i][j] = 0.f;
    for (int k0 = 0; k0 < DF; k0 += 8) {
        float4 av = make_float4(0.f, 0.f, 0.f, 0.f);
        if (arow) av = *(const float4*)(arow + k0 + akq);
        float4 bv = *(const float4*)(B + (size_t)(k0 + bk) * DM + n0 + bn);
        As[akq + 0][am] = av.x; As[akq + 1][am] = av.y;
        As[akq + 2][am] = av.z; As[akq + 3][am] = av.w;
        *(float4*)&Bs[bk][bn] = bv;
        __syncthreads();
        #pragma unroll
        for (int kk = 0; kk < 8; kk++) {
            float a[8], b[8];
            #pragma unroll
            for (int i = 0; i < 8; i++) a[i] = As[kk][ty * 8 + i];
            #pragma unroll
            for (int j = 0; j < 8; j++) b[j] = Bs[kk][tx * 8 + j];
            #pragma unroll
            for (int i = 0; i < 8; i++)
                #pragma unroll
                for (int j = 0; j < 8; j++) acc[i][j] += a[i] * b[j];
        }
        __syncthreads();
    }
    const float* bb = b2 + (size_t)e * DM + n0 + tx * 8;
    float4 b2lo = *(const float4*)(bb);
    float4 b2hi = *(const float4*)(bb + 4);
    #pragma unroll
    for (int i = 0; i < 8; i++) {
        int m = m0 + ty * 8 + i;
        if (m < cnt) {
            int tok = g_list[off + m];
            float* orow = out + (size_t)tok * DM + n0 + tx * 8;
            float4 v0, v1;
            v0.x = acc[i][0] + b2lo.x; v0.y = acc[i][1] + b2lo.y;
            v0.z = acc[i][2] + b2lo.z; v0.w = acc[i][3] + b2lo.w;
            v1.x = acc[i][4] + b2hi.x; v1.y = acc[i][5] + b2hi.y;
            v1.z = acc[i][6] + b2hi.z; v1.w = acc[i][7] + b2hi.w;
            *(float4*)(orow) = v0; *(float4*)(orow + 4) = v1;
        }
    }
}

// -------------------------------- launch -------------------------------------
extern "C" void kernel_launch(void* const* d_in, const int* in_sizes, int n_in,
                              void* d_out, int out_size)
{
    const float* X   = (const float*)d_in[0];
    const int*   idx = (const int*)d_in[1];
    const float* W1  = (const float*)d_in[2];
    const float* b1  = (const float*)d_in[3];
    const float* W2  = (const float*)d_in[4];
    const float* b2  = (const float*)d_in[5];
    float*       out = (float*)d_out;
    (void)in_sizes; (void)n_in; (void)out_size;

    k_route0<<<1, 32>>>();
    k_route1<<<(NTOK + 255) / 256, 256>>>(idx);
    k_route2<<<1, 32>>>();
    k_route3<<<(NTOK + 255) / 256, 256>>>(idx);

    k_probe<<<1, 32>>>(X, W1);

    k_convX<<<NTOK * DM / 4 / 256, 256>>>(X);
    k_convW<<<dim3(DM / 64, DF / 64, NE), 256>>>(W1, gW1h, gW1l, DM, DF);
    k_convW<<<dim3(DF / 64, DM / 64, NE), 256>>>(W2, gW2h, gW2l, DF, DM);

    // fast path (g_h / gH / gW / gX accessed as device globals inside)
    k_mma<0><<<dim3((NTOK / 128) * (DF / 128), 1, NE), 256>>>(b1, out);
    k_mma<1><<<dim3((NTOK / 128) * (DM / 128), 1, NE), 256>>>(b2, out);

    // verify 8 sampled outputs end-to-end; on mismatch clears g_ok
    k_check<<<8, 256>>>(X, idx, W1, b1, W2, b2, out);

    // fallback (runs iff g_ok == 0)
    k_gemm1<<<dim3(NTOK / 128, DF / 128, NE), 256>>>(X, W1, b1);
    k_gemm2<<<dim3(NTOK / 128, DM / 128, NE), 256>>>(W2, b2, out);
}

// round 14
// speedup vs baseline: 2.8370x; 2.8370x over previous
#include <cuda_runtime.h>
#include <cuda_bf16.h>
#include <math.h>
#include <stdint.h>

#define NTOK 16384
#define DM   1024
#define DF   4096
#define NE   8

__device__ int   g_cnt[NE], g_off[NE], g_fill[NE], g_list[NTOK];
__device__ int   g_ok;
__device__ float g_h[(size_t)NTOK * DF];   // 256MB fp32 H

__device__ __forceinline__ void mma16816(float* c, const uint32_t* a, const uint32_t* b) {
    asm volatile("mma.sync.aligned.m16n8k16.row.col.f32.bf16.bf16.f32 "
                 "{%0,%1,%2,%3},{%4,%5,%6,%7},{%8,%9},{%0,%1,%2,%3};"
                 : "+f"(c[0]), "+f"(c[1]), "+f"(c[2]), "+f"(c[3])
                 : "r"(a[0]), "r"(a[1]), "r"(a[2]), "r"(a[3]), "r"(b[0]), "r"(b[1]));
}
// Bit-exact hi/lo split, 2 packed cvts instead of 4 scalar ones.
__device__ __forceinline__ void split2(float x0, float x1, uint32_t& hi, uint32_t& lo) {
    uint32_t h;
    asm("cvt.rn.bf16x2.f32 %0, %1, %2;" : "=r"(h) : "f"(x1), "f"(x0));
    float f0 = __uint_as_float(h << 16);
    float f1 = __uint_as_float(h & 0xffff0000u);
    uint32_t l;
    asm("cvt.rn.bf16x2.f32 %0, %1, %2;" : "=r"(l) : "f"(x1 - f1), "f"(x0 - f0));
    hi = h; lo = l;
}
__device__ __forceinline__ float gelu_tanh(float x) {
    float x3 = x * x * x;
    return 0.5f * x * (1.0f + tanhf(0.7978845608028654f * (x + 0.044715f * x3)));
}

// ------------------------------- routing ------------------------------------
__global__ void k_route0() { if (threadIdx.x < NE) { g_cnt[threadIdx.x] = 0; g_fill[threadIdx.x] = 0; } }
__global__ void k_route1(const int* __restrict__ idx) {
    int t = blockIdx.x * blockDim.x + threadIdx.x;
    if (t < NTOK) atomicAdd(&g_cnt[idx[t]], 1);
}
__global__ void k_route2() {
    if (threadIdx.x == 0) { int s = 0; for (int e = 0; e < NE; e++) { g_off[e] = s; s += g_cnt[e]; } }
}
__global__ void k_route3(const int* __restrict__ idx) {
    int t = blockIdx.x * blockDim.x + threadIdx.x;
    if (t < NTOK) { int e = idx[t]; int p = atomicAdd(&g_fill[e], 1); g_list[g_off[e] + p] = t; }
}

// ---- probe: validates HMMA + fragment maps + conversion on real data ----
__global__ void k_probe(const float* __restrict__ X, const float* __restrict__ W1) {
    int lane = threadIdx.x & 31;
    int g = lane >> 2, tg = lane & 3;
    uint32_t ah[4], al[4], bh[2], bl[2];
    split2(X[(size_t)g * DM + 2 * tg],            X[(size_t)g * DM + 2 * tg + 1],       ah[0], al[0]);
    split2(X[(size_t)(g + 8) * DM + 2 * tg],      X[(size_t)(g + 8) * DM + 2 * tg + 1], ah[1], al[1]);
    split2(X[(size_t)g * DM + 2 * tg + 8],        X[(size_t)g * DM + 2 * tg + 9],       ah[2], al[2]);
    split2(X[(size_t)(g + 8) * DM + 2 * tg + 8],  X[(size_t)(g + 8) * DM + 2 * tg + 9], ah[3], al[3]);
    split2(W1[(size_t)(2 * tg) * DF + g],     W1[(size_t)(2 * tg + 1) * DF + g], bh[0], bl[0]);
    split2(W1[(size_t)(2 * tg + 8) * DF + g], W1[(size_t)(2 * tg + 9) * DF + g], bh[1], bl[1]);
    float c[4] = {0.f, 0.f, 0.f, 0.f};
    mma16816(c, ah, bh);
    mma16816(c, ah, bl);
    mma16816(c, al, bh);
    float r0 = 0.f, r1 = 0.f, r2 = 0.f, r3 = 0.f;
    for (int k = 0; k < 16; k++) {
        float w0 = W1[(size_t)k * DF + 2 * tg], w1 = W1[(size_t)k * DF + 2 * tg + 1];
        float xa = X[(size_t)g * DM + k], xb = X[(size_t)(g + 8) * DM + k];
        r0 += xa * w0; r1 += xa * w1; r2 += xb * w0; r3 += xb * w1;
    }
    float err = fmaxf(fmaxf(fabsf(c[0] - r0), fabsf(c[1] - r1)),
                      fmaxf(fabsf(c[2] - r2), fabsf(c[3] - r3)));
    float mag = fabsf(r0) + fabsf(r1) + fabsf(r2) + fabsf(r3);
    unsigned okm = __ballot_sync(0xffffffffu, err < 5e-3f);
    unsigned nzm = __ballot_sync(0xffffffffu, mag > 1e-3f);
    if (lane == 0) g_ok = (okm == 0xffffffffu && nzm != 0u) ? 1 : 0;
}

// ================== FAST PATH: HMMA hi/lo grouped GEMM =======================
// Exactly R12's validated kernel, with SMEM double-buffering (one sync/chunk).
// BM=BN=128, BK=16. 2 stages x 20KB. Row stride 10 words.
// Stage word offsets: Ah@0, Al@1280, Bh@2560, Bl@3840; stage 1 at +5120.
template <int MODE>
__global__ __launch_bounds__(256, 1) void k_mma(const float* __restrict__ Xin,
                                                const float* __restrict__ Bsrc,
                                                const float* __restrict__ bias,
                                                float* __restrict__ out) {
    if (!g_ok) return;
    __shared__ uint32_t sm4[10240];
    const int tid = threadIdx.x, wid = tid >> 5, lane = tid & 31;
    const int e = blockIdx.z, lin = blockIdx.x;
    int mi, ni;
    if (MODE == 0) { mi = ((lin >> 9) << 4) | (lin & 15); ni = (lin & 511) >> 4; }
    else           { mi = ((lin >> 7) << 4) | (lin & 15); ni = (lin & 127) >> 4; }
    const int cnt = g_cnt[e], m0 = mi * 128;
    if (m0 >= cnt) return;
    const int off = g_off[e], n0 = ni * 128;
    const int K = MODE ? DF : DM;
    const int ldB = MODE ? DM : DF;
    const int nk = K / 16;

    const int r = tid >> 1, s = tid & 1;
    const bool v = (m0 + r) < cnt;
    const float* aRow;
    if (MODE == 0) aRow = Xin + (v ? (size_t)g_list[off + m0 + r] * DM : 0);
    else           aRow = g_h + (size_t)(off + m0 + (v ? r : 0)) * DF;
    const int kp = tid >> 5;
    const float* bBase = Bsrc + (size_t)e * DM * DF;

    const int wm = wid & 1, wn = wid >> 1;
    const int g = lane >> 2, tg = lane & 3;

    float acc[4][4][4];
    #pragma unroll
    for (int i = 0; i < 4; i++)
        #pragma unroll
        for (int j = 0; j < 4; j++)
            #pragma unroll
            for (int q = 0; q < 4; q++) acc[i][j][q] = 0.f;

    float4 ra0, ra1;
    float  wb0[4], wb1[4];

    auto gload = [&](int c) {
        const int k0 = c * 16;
        if (v) { ra0 = *(const float4*)(aRow + k0 + s * 8); ra1 = *(const float4*)(aRow + k0 + s * 8 + 4); }
        else   { ra0 = make_float4(0.f, 0.f, 0.f, 0.f); ra1 = ra0; }
        const float* b0 = bBase + (size_t)(k0 + 2 * kp) * ldB + n0 + lane;
        const float* b1 = b0 + ldB;
        #pragma unroll
        for (int j = 0; j < 4; j++) { wb0[j] = b0[32 * j]; wb1[j] = b1[32 * j]; }
    };
    auto sstore = [&](int st) {
        const int base = st * 5120;
        uint32_t h0, l0, h1, l1, h2, l2, h3, l3;
        split2(ra0.x, ra0.y, h0, l0); split2(ra0.z, ra0.w, h1, l1);
        split2(ra1.x, ra1.y, h2, l2); split2(ra1.z, ra1.w, h3, l3);
        const int d = base + r * 10 + s * 4;
        *(uint2*)&sm4[d]        = make_uint2(h0, h1);
        *(uint2*)&sm4[d + 2]    = make_uint2(h2, h3);
        *(uint2*)&sm4[d + 1280] = make_uint2(l0, l1);
        *(uint2*)&sm4[d + 1282] = make_uint2(l2, l3);
        #pragma unroll
        for (int j = 0; j < 4; j++) {
            uint32_t hh, ll;
            split2(wb0[j], wb1[j], hh, ll);
            const int n = lane + 32 * j;
            sm4[base + 2560 + n * 10 + kp] = hh;
            sm4[base + 3840 + n * 10 + kp] = ll;
        }
    };

    gload(0); sstore(0);
    __syncthreads();

    for (int c = 0; c < nk; c++) {
        const bool more = (c + 1 < nk);
        if (more) gload(c + 1);

        const int st = (c & 1) * 5120;
        uint32_t Bh[4][2], Bl[4][2];
        #pragma unroll
        for (int j = 0; j < 4; j++) {
            const int nb = st + 2560 + (wn * 32 + j * 8 + g) * 10 + tg;
            Bh[j][0] = sm4[nb];        Bh[j][1] = sm4[nb + 4];
            Bl[j][0] = sm4[nb + 1280]; Bl[j][1] = sm4[nb + 1284];
        }
        #pragma unroll
        for (int i = 0; i < 4; i++) {
            const int ab = st + (wm * 64 + i * 16 + g) * 10 + tg;
            uint32_t ah[4] = { sm4[ab], sm4[ab + 80], sm4[ab + 4], sm4[ab + 84] };
            uint32_t al[4] = { sm4[ab + 1280], sm4[ab + 1360], sm4[ab + 1284], sm4[ab + 1364] };
            #pragma unroll
            for (int j = 0; j < 4; j++) {
                mma16816(acc[i][j], ah, Bh[j]);
                mma16816(acc[i][j], ah, Bl[j]);
                mma16816(acc[i][j], al, Bh[j]);
            }
        }
        if (more) sstore((c + 1) & 1);   // writes the OTHER stage; no WAR hazard
        __syncthreads();                 // single sync per chunk
    }

    const float* be = bias + (size_t)e * (MODE ? DM : DF);
    #pragma unroll
    for (int i = 0; i < 4; i++) {
        #pragma unroll
        for (int j = 0; j < 4; j++) {
            const int n  = n0 + wn * 32 + j * 8 + tg * 2;
            const int mL = m0 + wm * 64 + i * 16 + g;
            const int mH = mL + 8;
            const float bx = be[n], by = be[n + 1];
            if (MODE == 0) {
                if (mL < cnt) {
                    float2 vv = make_float2(gelu_tanh(acc[i][j][0] + bx), gelu_tanh(acc[i][j][1] + by));
                    *(float2*)(g_h + (size_t)(off + mL) * DF + n) = vv;
                }
                if (mH < cnt) {
                    float2 vv = make_float2(gelu_tanh(acc[i][j][2] + bx), gelu_tanh(acc[i][j][3] + by));
                    *(float2*)(g_h + (size_t)(off + mH) * DF + n) = vv;
                }
            } else {
                if (mL < cnt) {
                    float2 vv = make_float2(acc[i][j][0] + bx, acc[i][j][1] + by);
                    *(float2*)(out + (size_t)g_list[off + mL] * DM + n) = vv;
                }
                if (mH < cnt) {
                    float2 vv = make_float2(acc[i][j][2] + bx, acc[i][j][3] + by);
                    *(float2*)(out + (size_t)g_list[off + mH] * DM + n) = vv;
                }
            }
        }
    }
}

// ---- end-to-end checker: 8 sampled outputs recomputed in fp32; bad -> g_ok=0 ----
__global__ __launch_bounds__(256) void k_check(const float* __restrict__ X,
                                               const int* __restrict__ idx,
                                               const float* __restrict__ W1,
                                               const float* __restrict__ b1,
                                               const float* __restrict__ W2,
                                               const float* __restrict__ b2,
                                               const float* __restrict__ out) {
    if (!g_ok) return;
    __shared__ float red[256];
    int tid = threadIdx.x, sA = blockIdx.x;
    int t = sA * 2048 + 7;
    int n = (sA * 131 + 9) & (DM - 1);
    int e = idx[t];
    const float* xr = X + (size_t)t * DM;
    const float* w1 = W1 + (size_t)e * DM * DF;
    const float* w2 = W2 + (size_t)e * DF * DM;
    int f0 = tid * 16;
    float hs[16];
    #pragma unroll
    for (int u = 0; u < 16; u++) hs[u] = b1[(size_t)e * DF + f0 + u];
    for (int k = 0; k < DM; k++) {
        float xk = xr[k];
        const float* wr = w1 + (size_t)k * DF + f0;
        #pragma unroll
        for (int u = 0; u < 16; u++) hs[u] += xk * wr[u];
    }
    float accs = 0.f;
    #pragma unroll
    for (int u = 0; u < 16; u++) accs += gelu_tanh(hs[u]) * w2[(size_t)(f0 + u) * DM + n];
    red[tid] = accs;
    __syncthreads();
    for (int st = 128; st > 0; st >>= 1) { if (tid < st) red[tid] += red[tid + st]; __syncthreads(); }
    if (tid == 0) {
        float ref = red[0] + b2[(size_t)e * DM + n];
        float got = out[(size_t)t * DM + n];
        if (fabsf(got - ref) > 0.05f + 0.02f * fabsf(ref)) g_ok = 0;
    }
}

// =================== FALLBACK: proven FFMA GEMMs (6.9ms) =====================
__global__ __launch_bounds__(256, 2) void k_gemm1(
    const float* __restrict__ X, const float* __restrict__ W1,
    const float* __restrict__ b1)
{
    if (g_ok) return;
    int e = blockIdx.z, cnt = g_cnt[e], m0 = blockIdx.x * 128;
    if (m0 >= cnt) return;
    int off = g_off[e], n0 = blockIdx.y * 128;
    const float* B = W1 + (size_t)e * DM * DF;
    __shared__ float As[8][128];
    __shared__ float Bs[8][128];
    int tid = threadIdx.x, tx = tid & 15, ty = tid >> 4;
    int am = tid >> 1, akq = (tid & 1) * 4, mg = m0 + am;
    const float* arow = (mg < cnt) ? (X + (size_t)g_list[off + mg] * DM) : nullptr;
    int bk = tid >> 5, bn = (tid & 31) * 4;
    float acc[8][8];
    #pragma unroll
    for (int i = 0; i < 8; i++)
        #pragma unroll
        for (int j = 0; j < 8; j++) acc[i][j] = 0.f;
    for (int k0 = 0; k0 < DM; k0 += 8) {
        float4 av = make_float4(0.f, 0.f, 0.f, 0.f);
        if (arow) av = *(const float4*)(arow + k0 + akq);
        float4 bv = *(const float4*)(B + (size_t)(k0 + bk) * DF + n0 + bn);
        As[akq + 0][am] = av.x; As[akq + 1][am] = av.y;
        As[akq + 2][am] = av.z; As[akq + 3][am] = av.w;
        *(float4*)&Bs[bk][bn] = bv;
        __syncthreads();
        #pragma unroll
        for (int kk = 0; kk < 8; kk++) {
            float a[8], b[8];
            #pragma unroll
            for (int i = 0; i < 8; i++) a[i] = As[kk][ty * 8 + i];
            #pragma unroll
            for (int j = 0; j < 8; j++) b[j] = Bs[kk][tx * 8 + j];
            #pragma unroll
            for (int i = 0; i < 8; i++)
                #pragma unroll
                for (int j = 0; j < 8; j++) acc[i][j] += a[i] * b[j];
        }
        __syncthreads();
    }
    const float* bb = b1 + (size_t)e * DF + n0 + tx * 8;
    float4 b1lo = *(const float4*)(bb);
    float4 b1hi = *(const float4*)(bb + 4);
    #pragma unroll
    for (int i = 0; i < 8; i++) {
        int m = m0 + ty * 8 + i;
        if (m < cnt) {
            float* hrow = g_h + (size_t)(off + m) * DF + n0 + tx * 8;
            float4 v0, v1;
            v0.x = gelu_tanh(acc[i][0] + b1lo.x); v0.y = gelu_tanh(acc[i][1] + b1lo.y);
            v0.z = gelu_tanh(acc[i][2] + b1lo.z); v0.w = gelu_tanh(acc[i][3] + b1lo.w);
            v1.x = gelu_tanh(acc[i][4] + b1hi.x); v1.y = gelu_tanh(acc[i][5] + b1hi.y);
            v1.z = gelu_tanh(acc[i][6] + b1hi.z); v1.w = gelu_tanh(acc[i][7] + b1hi.w);
            *(float4*)(hrow) = v0; *(float4*)(hrow + 4) = v1;
        }
    }
}

__global__ __launch_bounds__(256, 2) void k_gemm2(
    const float* __restrict__ W2, const float* __restrict__ b2,
    float* __restrict__ out)
{
    if (g_ok) return;
    int e = blockIdx.z, cnt = g_cnt[e], m0 = blockIdx.x * 128;
    if (m0 >= cnt) return;
    int off = g_off[e], n0 = blockIdx.y * 128;
    const float* B = W2 + (size_t)e * DF * DM;
    __shared__ float As[8][128];
    __shared__ float Bs[8][128];
    int tid = threadIdx.x, tx = tid & 15, ty = tid >> 4;
    int am = tid >> 1, akq = (tid & 1) * 4, mg = m0 + am;
    const float* arow = (mg < cnt) ? (g_h + (size_t)(off + mg) * DF) : nullptr;
    int bk = tid >> 5, bn = (tid & 31) * 4;
    float acc[8][8];
    #pragma unroll
    for (int i = 0; i < 8; i++)
        #pragma unroll
        for (int j = 0; j < 8; j++) acc[i][j] = 0.f;
    for (int k0 = 0; k0 < DF; k0 += 8) {
        float4 av = make_float4(0.f, 0.f, 0.f, 0.f);
        if (arow) av = *(const float4*)(arow + k0 + akq);
        float4 bv = *(const float4*)(B + (size_t)(k0 + bk) * DM + n0 + bn);
        As[akq + 0][am] = av.x; As[akq + 1][am] = av.y;
        As[akq + 2][am] = av.z; As[akq + 3][am] = av.w;
        *(float4*)&Bs[bk][bn] = bv;
        __syncthreads();
        #pragma unroll
        for (int kk = 0; kk < 8; kk++) {
            float a[8], b[8];
            #pragma unroll
            for (int i = 0; i < 8; i++) a[i] = As[kk][ty * 8 + i];
            #pragma unroll
            for (int j = 0; j < 8; j++) b[j] = Bs[kk][tx * 8 + j];
            #pragma unroll
            for (int i = 0; i < 8; i++)
                #pragma unroll
                for (int j = 0; j < 8; j++) acc[i][j] += a[i] * b[j];
        }
        __syncthreads();
    }
    const float* bb = b2 + (size_t)e * DM + n0 + tx * 8;
    float4 b2lo = *(const float4*)(bb);
    float4 b2hi = *(const float4*)(bb + 4);
    #pragma unroll
    for (int i = 0; i < 8; i++) {
        int m = m0 + ty * 8 + i;
        if (m < cnt) {
            int tok = g_list[off + m];
            float* orow = out + (size_t)tok * DM + n0 + tx * 8;
            float4 v0, v1;
            v0.x = acc[i][0] + b2lo.x; v0.y = acc[i][1] + b2lo.y;
            v0.z = acc[i][2] + b2lo.z; v0.w = acc[i][3] + b2lo.w;
            v1.x = acc[i][4] + b2hi.x; v1.y = acc[i][5] + b2hi.y;
            v1.z = acc[i][6] + b2hi.z; v1.w = acc[i][7] + b2hi.w;
            *(float4*)(orow) = v0; *(float4*)(orow + 4) = v1;
        }
    }
}

// -------------------------------- launch -------------------------------------
extern "C" void kernel_launch(void* const* d_in, const int* in_sizes, int n_in,
                              void* d_out, int out_size)
{
    const float* X   = (const float*)d_in[0];
    const int*   idx = (const int*)d_in[1];
    const float* W1  = (const float*)d_in[2];
    const float* b1  = (const float*)d_in[3];
    const float* W2  = (const float*)d_in[4];
    const float* b2  = (const float*)d_in[5];
    float*       out = (float*)d_out;
    (void)in_sizes; (void)n_in; (void)out_size;

    k_route0<<<1, 32>>>();
    k_route1<<<(NTOK + 255) / 256, 256>>>(idx);
    k_route2<<<1, 32>>>();
    k_route3<<<(NTOK + 255) / 256, 256>>>(idx);

    k_probe<<<1, 32>>>(X, W1);

    k_mma<0><<<dim3((NTOK / 128) * (DF / 128), 1, NE), 256>>>(X, W1, b1, out);
    k_mma<1><<<dim3((NTOK / 128) * (DM / 128), 1, NE), 256>>>(X, W2, b2, out);

    k_check<<<8, 256>>>(X, idx, W1, b1, W2, b2, out);

    k_gemm1<<<dim3(NTOK / 128, DF / 128, NE), 256>>>(X, W1, b1);
    k_gemm2<<<dim3(NTOK / 128, DM / 128, NE), 256>>>(W2, b2, out);
}

// round 16
// speedup vs baseline: 3.4210x; 1.2058x over previous
#include <cuda_runtime.h>
#include <cuda_bf16.h>
#include <math.h>
#include <stdint.h>

#define NTOK 16384
#define DM   1024
#define DF   4096
#define NE   8

__device__ int   g_cnt[NE], g_off[NE], g_fill[NE], g_list[NTOK];
__device__ int   g_ok;
__device__ float g_h[(size_t)NTOK * DF];   // 256MB fp32 H

__device__ __forceinline__ void mma16816(float* c, const uint32_t* a, const uint32_t* b) {
    asm volatile("mma.sync.aligned.m16n8k16.row.col.f32.bf16.bf16.f32 "
                 "{%0,%1,%2,%3},{%4,%5,%6,%7},{%8,%9},{%0,%1,%2,%3};"
                 : "+f"(c[0]), "+f"(c[1]), "+f"(c[2]), "+f"(c[3])
                 : "r"(a[0]), "r"(a[1]), "r"(a[2]), "r"(a[3]), "r"(b[0]), "r"(b[1]));
}
// Bit-exact hi/lo split via packed cvt.
__device__ __forceinline__ void split2(float x0, float x1, uint32_t& hi, uint32_t& lo) {
    uint32_t h;
    asm("cvt.rn.bf16x2.f32 %0, %1, %2;" : "=r"(h) : "f"(x1), "f"(x0));
    float f0 = __uint_as_float(h << 16);
    float f1 = __uint_as_float(h & 0xffff0000u);
    uint32_t l;
    asm("cvt.rn.bf16x2.f32 %0, %1, %2;" : "=r"(l) : "f"(x1 - f1), "f"(x0 - f0));
    hi = h; lo = l;
}
__device__ __forceinline__ float gelu_tanh(float x) {
    float x3 = x * x * x;
    return 0.5f * x * (1.0f + tanhf(0.7978845608028654f * (x + 0.044715f * x3)));
}

// ------------------------------- routing ------------------------------------
__global__ void k_route0() { if (threadIdx.x < NE) { g_cnt[threadIdx.x] = 0; g_fill[threadIdx.x] = 0; } }
__global__ void k_route1(const int* __restrict__ idx) {
    int t = blockIdx.x * blockDim.x + threadIdx.x;
    if (t < NTOK) atomicAdd(&g_cnt[idx[t]], 1);
}
__global__ void k_route2() {
    if (threadIdx.x == 0) { int s = 0; for (int e = 0; e < NE; e++) { g_off[e] = s; s += g_cnt[e]; } }
}
__global__ void k_route3(const int* __restrict__ idx) {
    int t = blockIdx.x * blockDim.x + threadIdx.x;
    if (t < NTOK) { int e = idx[t]; int p = atomicAdd(&g_fill[e], 1); g_list[g_off[e] + p] = t; }
}

// ---- probe: validates HMMA + fragment maps + conversion on real data ----
__global__ void k_probe(const float* __restrict__ X, const float* __restrict__ W1) {
    int lane = threadIdx.x & 31;
    int g = lane >> 2, tg = lane & 3;
    uint32_t ah[4], al[4], bh[2], bl[2];
    split2(X[(size_t)g * DM + 2 * tg],            X[(size_t)g * DM + 2 * tg + 1],       ah[0], al[0]);
    split2(X[(size_t)(g + 8) * DM + 2 * tg],      X[(size_t)(g + 8) * DM + 2 * tg + 1], ah[1], al[1]);
    split2(X[(size_t)g * DM + 2 * tg + 8],        X[(size_t)g * DM + 2 * tg + 9],       ah[2], al[2]);
    split2(X[(size_t)(g + 8) * DM + 2 * tg + 8],  X[(size_t)(g + 8) * DM + 2 * tg + 9], ah[3], al[3]);
    split2(W1[(size_t)(2 * tg) * DF + g],     W1[(size_t)(2 * tg + 1) * DF + g], bh[0], bl[0]);
    split2(W1[(size_t)(2 * tg + 8) * DF + g], W1[(size_t)(2 * tg + 9) * DF + g], bh[1], bl[1]);
    float c[4] = {0.f, 0.f, 0.f, 0.f};
    mma16816(c, ah, bh);
    mma16816(c, ah, bl);
    mma16816(c, al, bh);
    float r0 = 0.f, r1 = 0.f, r2 = 0.f, r3 = 0.f;
    for (int k = 0; k < 16; k++) {
        float w0 = W1[(size_t)k * DF + 2 * tg], w1 = W1[(size_t)k * DF + 2 * tg + 1];
        float xa = X[(size_t)g * DM + k], xb = X[(size_t)(g + 8) * DM + k];
        r0 += xa * w0; r1 += xa * w1; r2 += xb * w0; r3 += xb * w1;
    }
    float err = fmaxf(fmaxf(fabsf(c[0] - r0), fabsf(c[1] - r1)),
                      fmaxf(fabsf(c[2] - r2), fabsf(c[3] - r3)));
    float mag = fabsf(r0) + fabsf(r1) + fabsf(r2) + fabsf(r3);
    unsigned okm = __ballot_sync(0xffffffffu, err < 5e-3f);
    unsigned nzm = __ballot_sync(0xffffffffu, mag > 1e-3f);
    if (lane == 0) g_ok = (okm == 0xffffffffu && nzm != 0u) ? 1 : 0;
}

// ================== FAST PATH: HMMA hi/lo grouped GEMM =======================
// R14's validated kernel; only change: occupancy 2 (launch_bounds 256,2).
// BM=BN=128, BK=16. 2 stages x 20KB. Row stride 10 words.
template <int MODE>
__global__ __launch_bounds__(256, 2) void k_mma(const float* __restrict__ Xin,
                                                const float* __restrict__ Bsrc,
                                                const float* __restrict__ bias,
                                                float* __restrict__ out) {
    if (!g_ok) return;
    __shared__ uint32_t sm4[10240];
    const int tid = threadIdx.x, wid = tid >> 5, lane = tid & 31;
    const int e = blockIdx.z, lin = blockIdx.x;
    int mi, ni;
    if (MODE == 0) { mi = ((lin >> 9) << 4) | (lin & 15); ni = (lin & 511) >> 4; }
    else           { mi = ((lin >> 7) << 4) | (lin & 15); ni = (lin & 127) >> 4; }
    const int cnt = g_cnt[e], m0 = mi * 128;
    if (m0 >= cnt) return;
    const int off = g_off[e], n0 = ni * 128;
    const int K = MODE ? DF : DM;
    const int ldB = MODE ? DM : DF;
    const int nk = K / 16;

    const int r = tid >> 1, s = tid & 1;
    const bool v = (m0 + r) < cnt;
    const float* aRow;
    if (MODE == 0) aRow = Xin + (v ? (size_t)g_list[off + m0 + r] * DM : 0);
    else           aRow = g_h + (size_t)(off + m0 + (v ? r : 0)) * DF;
    const int kp = tid >> 5;
    const float* bBase = Bsrc + (size_t)e * DM * DF;

    const int wm = wid & 1, wn = wid >> 1;
    const int g = lane >> 2, tg = lane & 3;

    float acc[4][4][4];
    #pragma unroll
    for (int i = 0; i < 4; i++)
        #pragma unroll
        for (int j = 0; j < 4; j++)
            #pragma unroll
            for (int q = 0; q < 4; q++) acc[i][j][q] = 0.f;

    float4 ra0, ra1;
    float  wb0[4], wb1[4];

    auto gload = [&](int c) {
        const int k0 = c * 16;
        if (v) { ra0 = *(const float4*)(aRow + k0 + s * 8); ra1 = *(const float4*)(aRow + k0 + s * 8 + 4); }
        else   { ra0 = make_float4(0.f, 0.f, 0.f, 0.f); ra1 = ra0; }
        const float* b0 = bBase + (size_t)(k0 + 2 * kp) * ldB + n0 + lane;
        const float* b1 = b0 + ldB;
        #pragma unroll
        for (int j = 0; j < 4; j++) { wb0[j] = b0[32 * j]; wb1[j] = b1[32 * j]; }
    };
    auto sstore = [&](int st) {
        const int base = st * 5120;
        uint32_t h0, l0, h1, l1, h2, l2, h3, l3;
        split2(ra0.x, ra0.y, h0, l0); split2(ra0.z, ra0.w, h1, l1);
        split2(ra1.x, ra1.y, h2, l2); split2(ra1.z, ra1.w, h3, l3);
        const int d = base + r * 10 + s * 4;
        *(uint2*)&sm4[d]        = make_uint2(h0, h1);
        *(uint2*)&sm4[d + 2]    = make_uint2(h2, h3);
        *(uint2*)&sm4[d + 1280] = make_uint2(l0, l1);
        *(uint2*)&sm4[d + 1282] = make_uint2(l2, l3);
        #pragma unroll
        for (int j = 0; j < 4; j++) {
            uint32_t hh, ll;
            split2(wb0[j], wb1[j], hh, ll);
            const int n = lane + 32 * j;
            sm4[base + 2560 + n * 10 + kp] = hh;
            sm4[base + 3840 + n * 10 + kp] = ll;
        }
    };

    gload(0); sstore(0);
    __syncthreads();

    for (int c = 0; c < nk; c++) {
        const bool more = (c + 1 < nk);
        if (more) gload(c + 1);

        const int st = (c & 1) * 5120;
        uint32_t Bh[4][2], Bl[4][2];
        #pragma unroll
        for (int j = 0; j < 4; j++) {
            const int nb = st + 2560 + (wn * 32 + j * 8 + g) * 10 + tg;
            Bh[j][0] = sm4[nb];        Bh[j][1] = sm4[nb + 4];
            Bl[j][0] = sm4[nb + 1280]; Bl[j][1] = sm4[nb + 1284];
        }
        #pragma unroll
        for (int i = 0; i < 4; i++) {
            const int ab = st + (wm * 64 + i * 16 + g) * 10 + tg;
            uint32_t ah[4] = { sm4[ab], sm4[ab + 80], sm4[ab + 4], sm4[ab + 84] };
            uint32_t al[4] = { sm4[ab + 1280], sm4[ab + 1360], sm4[ab + 1284], sm4[ab + 1364] };
            #pragma unroll
            for (int j = 0; j < 4; j++) {
                mma16816(acc[i][j], ah, Bh[j]);
                mma16816(acc[i][j], ah, Bl[j]);
                mma16816(acc[i][j], al, Bh[j]);
            }
        }
        if (more) sstore((c + 1) & 1);
        __syncthreads();
    }

    const float* be = bias + (size_t)e * (MODE ? DM : DF);
    #pragma unroll
    for (int i = 0; i < 4; i++) {
        #pragma unroll
        for (int j = 0; j < 4; j++) {
            const int n  = n0 + wn * 32 + j * 8 + tg * 2;
            const int mL = m0 + wm * 64 + i * 16 + g;
            const int mH = mL + 8;
            const float bx = be[n], by = be[n + 1];
            if (MODE == 0) {
                if (mL < cnt) {
                    float2 vv = make_float2(gelu_tanh(acc[i][j][0] + bx), gelu_tanh(acc[i][j][1] + by));
                    *(float2*)(g_h + (size_t)(off + mL) * DF + n) = vv;
                }
                if (mH < cnt) {
                    float2 vv = make_float2(gelu_tanh(acc[i][j][2] + bx), gelu_tanh(acc[i][j][3] + by));
                    *(float2*)(g_h + (size_t)(off + mH) * DF + n) = vv;
                }
            } else {
                if (mL < cnt) {
                    float2 vv = make_float2(acc[i][j][0] + bx, acc[i][j][1] + by);
                    *(float2*)(out + (size_t)g_list[off + mL] * DM + n) = vv;
                }
                if (mH < cnt) {
                    float2 vv = make_float2(acc[i][j][2] + bx, acc[i][j][3] + by);
                    *(float2*)(out + (size_t)g_list[off + mH] * DM + n) = vv;
                }
            }
        }
    }
}

// ---- end-to-end checker: 8 sampled outputs recomputed in fp32; bad -> g_ok=0 ----
__global__ __launch_bounds__(256) void k_check(const float* __restrict__ X,
                                               const int* __restrict__ idx,
                                               const float* __restrict__ W1,
                                               const float* __restrict__ b1,
                                               const float* __restrict__ W2,
                                               const float* __restrict__ b2,
                                               const float* __restrict__ out) {
    if (!g_ok) return;
    __shared__ float red[256];
    int tid = threadIdx.x, sA = blockIdx.x;
    int t = sA * 2048 + 7;
    int n = (sA * 131 + 9) & (DM - 1);
    int e = idx[t];
    const float* xr = X + (size_t)t * DM;
    const float* w1 = W1 + (size_t)e * DM * DF;
    const float* w2 = W2 + (size_t)e * DF * DM;
    int f0 = tid * 16;
    float hs[16];
    #pragma unroll
    for (int u = 0; u < 16; u++) hs[u] = b1[(size_t)e * DF + f0 + u];
    for (int k = 0; k < DM; k++) {
        float xk = xr[k];
        const float* wr = w1 + (size_t)k * DF + f0;
        #pragma unroll
        for (int u = 0; u < 16; u++) hs[u] += xk * wr[u];
    }
    float accs = 0.f;
    #pragma unroll
    for (int u = 0; u < 16; u++) accs += gelu_tanh(hs[u]) * w2[(size_t)(f0 + u) * DM + n];
    red[tid] = accs;
    __syncthreads();
    for (int st = 128; st > 0; st >>= 1) { if (tid < st) red[tid] += red[tid + st]; __syncthreads(); }
    if (tid == 0) {
        float ref = red[0] + b2[(size_t)e * DM + n];
        float got = out[(size_t)t * DM + n];
        if (fabsf(got - ref) > 0.05f + 0.02f * fabsf(ref)) g_ok = 0;
    }
}

// =================== FALLBACK: proven FFMA GEMMs (6.9ms) =====================
__global__ __launch_bounds__(256, 2) void k_gemm1(
    const float* __restrict__ X, const float* __restrict__ W1,
    const float* __restrict__ b1)
{
    if (g_ok) return;
    int e = blockIdx.z, cnt = g_cnt[e], m0 = blockIdx.x * 128;
    if (m0 >= cnt) return;
    int off = g_off[e], n0 = blockIdx.y * 128;
    const float* B = W1 + (size_t)e * DM * DF;
    __shared__ float As[8][128];
    __shared__ float Bs[8][128];
    int tid = threadIdx.x, tx = tid & 15, ty = tid >> 4;
    int am = tid >> 1, akq = (tid & 1) * 4, mg = m0 + am;
    const float* arow = (mg < cnt) ? (X + (size_t)g_list[off + mg] * DM) : nullptr;
    int bk = tid >> 5, bn = (tid & 31) * 4;
    float acc[8][8];
    #pragma unroll
    for (int i = 0; i < 8; i++)
        #pragma unroll
        for (int j = 0; j < 8; j++) acc[i][j] = 0.f;
    for (int k0 = 0; k0 < DM; k0 += 8) {
        float4 av = make_float4(0.f, 0.f, 0.f, 0.f);
        if (arow) av = *(const float4*)(arow + k0 + akq);
        float4 bv = *(const float4*)(B + (size_t)(k0 + bk) * DF + n0 + bn);
        As[akq + 0][am] = av.x; As[akq + 1][am] = av.y;
        As[akq + 2][am] = av.z; As[akq + 3][am] = av.w;
        *(float4*)&Bs[bk][bn] = bv;
        __syncthreads();
        #pragma unroll
        for (int kk = 0; kk < 8; kk++) {
            float a[8], b[8];
            #pragma unroll
            for (int i = 0; i < 8; i++) a[i] = As[kk][ty * 8 + i];
            #pragma unroll
            for (int j = 0; j < 8; j++) b[j] = Bs[kk][tx * 8 + j];
            #pragma unroll
            for (int i = 0; i < 8; i++)
                #pragma unroll
                for (int j = 0; j < 8; j++) acc[i][j] += a[i] * b[j];
        }
        __syncthreads();
    }
    const float* bb = b1 + (size_t)e * DF + n0 + tx * 8;
    float4 b1lo = *(const float4*)(bb);
    float4 b1hi = *(const float4*)(bb + 4);
    #pragma unroll
    for (int i = 0; i < 8; i++) {
        int m = m0 + ty * 8 + i;
        if (m < cnt) {
            float* hrow = g_h + (size_t)(off + m) * DF + n0 + tx * 8;
            float4 v0, v1;
            v0.x = gelu_tanh(acc[i][0] + b1lo.x); v0.y = gelu_tanh(acc[i][1] + b1lo.y);
            v0.z = gelu_tanh(acc[i][2] + b1lo.z); v0.w = gelu_tanh(acc[i][3] + b1lo.w);
            v1.x = gelu_tanh(acc[i][4] + b1hi.x); v1.y = gelu_tanh(acc[i][5] + b1hi.y);
            v1.z = gelu_tanh(acc[i][6] + b1hi.z); v1.w = gelu_tanh(acc[i][7] + b1hi.w);
            *(float4*)(hrow) = v0; *(float4*)(hrow + 4) = v1;
        }
    }
}

__global__ __launch_bounds__(256, 2) void k_gemm2(
    const float* __restrict__ W2, const float* __restrict__ b2,
    float* __restrict__ out)
{
    if (g_ok) return;
    int e = blockIdx.z, cnt = g_cnt[e], m0 = blockIdx.x * 128;
    if (m0 >= cnt) return;
    int off = g_off[e], n0 = blockIdx.y * 128;
    const float* B = W2 + (size_t)e * DF * DM;
    __shared__ float As[8][128];
    __shared__ float Bs[8][128];
    int tid = threadIdx.x, tx = tid & 15, ty = tid >> 4;
    int am = tid >> 1, akq = (tid & 1) * 4, mg = m0 + am;
    const float* arow = (mg < cnt) ? (g_h + (size_t)(off + mg) * DF) : nullptr;
    int bk = tid >> 5, bn = (tid & 31) * 4;
    float acc[8][8];
    #pragma unroll
    for (int i = 0; i < 8; i++)
        #pragma unroll
        for (int j = 0; j < 8; j++) acc[i][j] = 0.f;
    for (int k0 = 0; k0 < DF; k0 += 8) {
        float4 av = make_float4(0.f, 0.f, 0.f, 0.f);
        if (arow) av = *(const float4*)(arow + k0 + akq);
        float4 bv = *(const float4*)(B + (size_t)(k0 + bk) * DM + n0 + bn);
        As[akq + 0][am] = av.x; As[akq + 1][am] = av.y;
        As[akq + 2][am] = av.z; As[akq + 3][am] = av.w;
        *(float4*)&Bs[bk][bn] = bv;
        __syncthreads();
        #pragma unroll
        for (int kk = 0; kk < 8; kk++) {
            float a[8], b[8];
            #pragma unroll
            for (int i = 0; i < 8; i++) a[i] = As[kk][ty * 8 + i];
            #pragma unroll
            for (int j = 0; j < 8; j++) b[j] = Bs[kk][tx * 8 + j];
            #pragma unroll
            for (int i = 0; i < 8; i++)
                #pragma unroll
                for (int j = 0; j < 8; j++) acc[i][j] += a[i] * b[j];
        }
        __syncthreads();
    }
    const float* bb = b2 + (size_t)e * DM + n0 + tx * 8;
    float4 b2lo = *(const float4*)(bb);
    float4 b2hi = *(const float4*)(bb + 4);
    #pragma unroll
    for (int i = 0; i < 8; i++) {
        int m = m0 + ty * 8 + i;
        if (m < cnt) {
            int tok = g_list[off + m];
            float* orow = out + (size_t)tok * DM + n0 + tx * 8;
            float4 v0, v1;
            v0.x = acc[i][0] + b2lo.x; v0.y = acc[i][1] + b2lo.y;
            v0.z = acc[i][2] + b2lo.z; v0.w = acc[i][3] + b2lo.w;
            v1.x = acc[i][4] + b2hi.x; v1.y = acc[i][5] + b2hi.y;
            v1.z = acc[i][6] + b2hi.z; v1.w = acc[i][7] + b2hi.w;
            *(float4*)(orow) = v0; *(float4*)(orow + 4) = v1;
        }
    }
}

// -------------------------------- launch -------------------------------------
extern "C" void kernel_launch(void* const* d_in, const int* in_sizes, int n_in,
                              void* d_out, int out_size)
{
    const float* X   = (const float*)d_in[0];
    const int*   idx = (const int*)d_in[1];
    const float* W1  = (const float*)d_in[2];
    const float* b1  = (const float*)d_in[3];
    const float* W2  = (const float*)d_in[4];
    const float* b2  = (const float*)d_in[5];
    float*       out = (float*)d_out;
    (void)in_sizes; (void)n_in; (void)out_size;

    k_route0<<<1, 32>>>();
    k_route1<<<(NTOK + 255) / 256, 256>>>(idx);
    k_route2<<<1, 32>>>();
    k_route3<<<(NTOK + 255) / 256, 256>>>(idx);

    k_probe<<<1, 32>>>(X, W1);

    k_mma<0><<<dim3((NTOK / 128) * (DF / 128), 1, NE), 256>>>(X, W1, b1, out);
    k_mma<1><<<dim3((NTOK / 128) * (DM / 128), 1, NE), 256>>>(X, W2, b2, out);

    k_check<<<8, 256>>>(X, idx, W1, b1, W2, b2, out);

    k_gemm1<<<dim3(NTOK / 128, DF / 128, NE), 256>>>(X, W1, b1);
    k_gemm2<<<dim3(NTOK / 128, DM / 128, NE), 256>>>(W2, b2, out);
}

// round 17
// speedup vs baseline: 4.0406x; 1.1811x over previous
#include <cuda_runtime.h>
#include <cuda_bf16.h>
#include <math.h>
#include <stdint.h>

#define NTOK 16384
#define DM   1024
#define DF   4096
#define NE   8

__device__ int   g_cnt[NE], g_off[NE], g_fill[NE], g_list[NTOK];
__device__ int   g_ok;
__device__ float g_h[(size_t)NTOK * DF];   // 256MB fp32 H

__device__ __forceinline__ uint32_t smem_u32(const void* p) {
    uint32_t a;
    asm("{ .reg .u64 t; cvta.to.shared.u64 t, %1; cvt.u32.u64 %0, t; }" : "=r"(a) : "l"(p));
    return a;
}
__device__ __forceinline__ void mma16816(float* c, const uint32_t* a, const uint32_t* b) {
    asm volatile("mma.sync.aligned.m16n8k16.row.col.f32.bf16.bf16.f32 "
                 "{%0,%1,%2,%3},{%4,%5,%6,%7},{%8,%9},{%0,%1,%2,%3};"
                 : "+f"(c[0]), "+f"(c[1]), "+f"(c[2]), "+f"(c[3])
                 : "r"(a[0]), "r"(a[1]), "r"(a[2]), "r"(a[3]), "r"(b[0]), "r"(b[1]));
}
__device__ __forceinline__ void ldsm4(uint32_t* r, uint32_t a) {
    asm volatile("ldmatrix.sync.aligned.m8n8.x4.shared.b16 {%0,%1,%2,%3}, [%4];"
                 : "=r"(r[0]), "=r"(r[1]), "=r"(r[2]), "=r"(r[3]) : "r"(a));
}
// Bit-exact hi/lo split via packed cvt.
__device__ __forceinline__ void split2(float x0, float x1, uint32_t& hi, uint32_t& lo) {
    uint32_t h;
    asm("cvt.rn.bf16x2.f32 %0, %1, %2;" : "=r"(h) : "f"(x1), "f"(x0));
    float f0 = __uint_as_float(h << 16);
    float f1 = __uint_as_float(h & 0xffff0000u);
    uint32_t l;
    asm("cvt.rn.bf16x2.f32 %0, %1, %2;" : "=r"(l) : "f"(x1 - f1), "f"(x0 - f0));
    hi = h; lo = l;
}
__device__ __forceinline__ float gelu_tanh(float x) {
    float x3 = x * x * x;
    return 0.5f * x * (1.0f + tanhf(0.7978845608028654f * (x + 0.044715f * x3)));
}

// ------------------------------- routing ------------------------------------
__global__ void k_route0() { if (threadIdx.x < NE) { g_cnt[threadIdx.x] = 0; g_fill[threadIdx.x] = 0; } }
__global__ void k_route1(const int* __restrict__ idx) {
    int t = blockIdx.x * blockDim.x + threadIdx.x;
    if (t < NTOK) atomicAdd(&g_cnt[idx[t]], 1);
}
__global__ void k_route2() {
    if (threadIdx.x == 0) { int s = 0; for (int e = 0; e < NE; e++) { g_off[e] = s; s += g_cnt[e]; } }
}
__global__ void k_route3(const int* __restrict__ idx) {
    int t = blockIdx.x * blockDim.x + threadIdx.x;
    if (t < NTOK) { int e = idx[t]; int p = atomicAdd(&g_fill[e], 1); g_list[g_off[e] + p] = t; }
}

// ---- probe: validates HMMA + conversion on real data ----
__global__ void k_probe(const float* __restrict__ X, const float* __restrict__ W1) {
    int lane = threadIdx.x & 31;
    int g = lane >> 2, tg = lane & 3;
    uint32_t ah[4], al[4], bh[2], bl[2];
    split2(X[(size_t)g * DM + 2 * tg],            X[(size_t)g * DM + 2 * tg + 1],       ah[0], al[0]);
    split2(X[(size_t)(g + 8) * DM + 2 * tg],      X[(size_t)(g + 8) * DM + 2 * tg + 1], ah[1], al[1]);
    split2(X[(size_t)g * DM + 2 * tg + 8],        X[(size_t)g * DM + 2 * tg + 9],       ah[2], al[2]);
    split2(X[(size_t)(g + 8) * DM + 2 * tg + 8],  X[(size_t)(g + 8) * DM + 2 * tg + 9], ah[3], al[3]);
    split2(W1[(size_t)(2 * tg) * DF + g],     W1[(size_t)(2 * tg + 1) * DF + g], bh[0], bl[0]);
    split2(W1[(size_t)(2 * tg + 8) * DF + g], W1[(size_t)(2 * tg + 9) * DF + g], bh[1], bl[1]);
    float c[4] = {0.f, 0.f, 0.f, 0.f};
    mma16816(c, ah, bh);
    mma16816(c, ah, bl);
    mma16816(c, al, bh);
    float r0 = 0.f, r1 = 0.f, r2 = 0.f, r3 = 0.f;
    for (int k = 0; k < 16; k++) {
        float w0 = W1[(size_t)k * DF + 2 * tg], w1 = W1[(size_t)k * DF + 2 * tg + 1];
        float xa = X[(size_t)g * DM + k], xb = X[(size_t)(g + 8) * DM + k];
        r0 += xa * w0; r1 += xa * w1; r2 += xb * w0; r3 += xb * w1;
    }
    float err = fmaxf(fmaxf(fabsf(c[0] - r0), fabsf(c[1] - r1)),
                      fmaxf(fabsf(c[2] - r2), fabsf(c[3] - r3)));
    float mag = fabsf(r0) + fabsf(r1) + fabsf(r2) + fabsf(r3);
    unsigned okm = __ballot_sync(0xffffffffu, err < 5e-3f);
    unsigned nzm = __ballot_sync(0xffffffffu, mag > 1e-3f);
    if (lane == 0) g_ok = (okm == 0xffffffffu && nzm != 0u) ? 1 : 0;
}

// ================== FAST PATH: HMMA hi/lo grouped GEMM =======================
// R16 kernel with: row stride 12 words (48B, 16B-aligned, conflict-free) and
// ldmatrix.x4 fragment loads (12 per warp-chunk instead of 48 scalar LDS).
// 2 stages x 24KB. Stage word layout: Ah@0, Al@1536, Bh@3072, Bl@4608.
template <int MODE>
__global__ __launch_bounds__(256, 2) void k_mma(const float* __restrict__ Xin,
                                                const float* __restrict__ Bsrc,
                                                const float* __restrict__ bias,
                                                float* __restrict__ out) {
    if (!g_ok) return;
    __shared__ __align__(16) uint32_t sm4[12288];
    const int tid = threadIdx.x, wid = tid >> 5, lane = tid & 31;
    const int e = blockIdx.z, lin = blockIdx.x;
    int mi, ni;
    if (MODE == 0) { mi = ((lin >> 9) << 4) | (lin & 15); ni = (lin & 511) >> 4; }
    else           { mi = ((lin >> 7) << 4) | (lin & 15); ni = (lin & 127) >> 4; }
    const int cnt = g_cnt[e], m0 = mi * 128;
    if (m0 >= cnt) return;
    const int off = g_off[e], n0 = ni * 128;
    const int K = MODE ? DF : DM;
    const int ldB = MODE ? DM : DF;
    const int nk = K / 16;

    const int r = tid >> 1, s = tid & 1;
    const bool v = (m0 + r) < cnt;
    const float* aRow;
    if (MODE == 0) aRow = Xin + (v ? (size_t)g_list[off + m0 + r] * DM : 0);
    else           aRow = g_h + (size_t)(off + m0 + (v ? r : 0)) * DF;
    const int kp = tid >> 5;
    const float* bBase = Bsrc + (size_t)e * DM * DF;

    const int wm = wid & 1, wn = wid >> 1;
    const int g = lane >> 2, tg = lane & 3;

    // ldmatrix byte addresses (per-warp lane maps; tiles per PTX x4 spec)
    const uint32_t smb = smem_u32(sm4);
    const uint32_t aAddr = smb + (uint32_t)((wm * 64 + (lane & 15)) * 12) * 4u
                               + (uint32_t)(lane >> 4) * 16u;
    const uint32_t bAddr = smb + 12288u
                               + (uint32_t)((wn * 32 + ((lane >> 4) & 1) * 8 + (lane & 7)) * 12) * 4u
                               + (uint32_t)((lane >> 3) & 1) * 16u;

    float acc[4][4][4];
    #pragma unroll
    for (int i = 0; i < 4; i++)
        #pragma unroll
        for (int j = 0; j < 4; j++)
            #pragma unroll
            for (int q = 0; q < 4; q++) acc[i][j][q] = 0.f;

    float4 ra0, ra1;
    float  wb0[4], wb1[4];

    auto gload = [&](int c) {
        const int k0 = c * 16;
        if (v) { ra0 = *(const float4*)(aRow + k0 + s * 8); ra1 = *(const float4*)(aRow + k0 + s * 8 + 4); }
        else   { ra0 = make_float4(0.f, 0.f, 0.f, 0.f); ra1 = ra0; }
        const float* b0 = bBase + (size_t)(k0 + 2 * kp) * ldB + n0 + lane;
        const float* b1 = b0 + ldB;
        #pragma unroll
        for (int j = 0; j < 4; j++) { wb0[j] = b0[32 * j]; wb1[j] = b1[32 * j]; }
    };
    auto sstore = [&](int stg) {
        const int base = stg * 6144;
        uint32_t h0, l0, h1, l1, h2, l2, h3, l3;
        split2(ra0.x, ra0.y, h0, l0); split2(ra0.z, ra0.w, h1, l1);
        split2(ra1.x, ra1.y, h2, l2); split2(ra1.z, ra1.w, h3, l3);
        const int d = base + r * 12 + s * 4;
        *(uint2*)&sm4[d]        = make_uint2(h0, h1);
        *(uint2*)&sm4[d + 2]    = make_uint2(h2, h3);
        *(uint2*)&sm4[d + 1536] = make_uint2(l0, l1);
        *(uint2*)&sm4[d + 1538] = make_uint2(l2, l3);
        #pragma unroll
        for (int j = 0; j < 4; j++) {
            uint32_t hh, ll;
            split2(wb0[j], wb1[j], hh, ll);
            const int n = lane + 32 * j;
            sm4[base + 3072 + n * 12 + kp] = hh;
            sm4[base + 4608 + n * 12 + kp] = ll;
        }
    };

    gload(0); sstore(0);
    __syncthreads();

    for (int c = 0; c < nk; c++) {
        const bool more = (c + 1 < nk);
        if (more) gload(c + 1);

        const uint32_t st = (uint32_t)(c & 1) * 24576u;   // stage byte offset
        uint32_t bh01[4], bh23[4], bl01[4], bl23[4];
        ldsm4(bh01, bAddr + st);
        ldsm4(bh23, bAddr + st + 768u);
        ldsm4(bl01, bAddr + st + 6144u);
        ldsm4(bl23, bAddr + st + 6144u + 768u);
        uint32_t Bh[4][2] = {{bh01[0], bh01[1]}, {bh01[2], bh01[3]},
                             {bh23[0], bh23[1]}, {bh23[2], bh23[3]}};
        uint32_t Bl[4][2] = {{bl01[0], bl01[1]}, {bl01[2], bl01[3]},
                             {bl23[0], bl23[1]}, {bl23[2], bl23[3]}};
        #pragma unroll
        for (int i = 0; i < 4; i++) {
            uint32_t ah[4], al[4];
            ldsm4(ah, aAddr + st + (uint32_t)i * 768u);
            ldsm4(al, aAddr + st + 6144u + (uint32_t)i * 768u);
            #pragma unroll
            for (int j = 0; j < 4; j++) {
                mma16816(acc[i][j], ah, Bh[j]);
                mma16816(acc[i][j], ah, Bl[j]);
                mma16816(acc[i][j], al, Bh[j]);
            }
        }
        if (more) sstore((c + 1) & 1);
        __syncthreads();
    }

    const float* be = bias + (size_t)e * (MODE ? DM : DF);
    #pragma unroll
    for (int i = 0; i < 4; i++) {
        #pragma unroll
        for (int j = 0; j < 4; j++) {
            const int n  = n0 + wn * 32 + j * 8 + tg * 2;
            const int mL = m0 + wm * 64 + i * 16 + g;
            const int mH = mL + 8;
            const float bx = be[n], by = be[n + 1];
            if (MODE == 0) {
                if (mL < cnt) {
                    float2 vv = make_float2(gelu_tanh(acc[i][j][0] + bx), gelu_tanh(acc[i][j][1] + by));
                    *(float2*)(g_h + (size_t)(off + mL) * DF + n) = vv;
                }
                if (mH < cnt) {
                    float2 vv = make_float2(gelu_tanh(acc[i][j][2] + bx), gelu_tanh(acc[i][j][3] + by));
                    *(float2*)(g_h + (size_t)(off + mH) * DF + n) = vv;
                }
            } else {
                if (mL < cnt) {
                    float2 vv = make_float2(acc[i][j][0] + bx, acc[i][j][1] + by);
                    *(float2*)(out + (size_t)g_list[off + mL] * DM + n) = vv;
                }
                if (mH < cnt) {
                    float2 vv = make_float2(acc[i][j][2] + bx, acc[i][j][3] + by);
                    *(float2*)(out + (size_t)g_list[off + mH] * DM + n) = vv;
                }
            }
        }
    }
}

// ---- end-to-end checker: 8 sampled outputs recomputed in fp32; bad -> g_ok=0 ----
__global__ __launch_bounds__(256) void k_check(const float* __restrict__ X,
                                               const int* __restrict__ idx,
                                               const float* __restrict__ W1,
                                               const float* __restrict__ b1,
                                               const float* __restrict__ W2,
                                               const float* __restrict__ b2,
                                               const float* __restrict__ out) {
    if (!g_ok) return;
    __shared__ float red[256];
    int tid = threadIdx.x, sA = blockIdx.x;
    int t = sA * 2048 + 7;
    int n = (sA * 131 + 9) & (DM - 1);
    int e = idx[t];
    const float* xr = X + (size_t)t * DM;
    const float* w1 = W1 + (size_t)e * DM * DF;
    const float* w2 = W2 + (size_t)e * DF * DM;
    int f0 = tid * 16;
    float hs[16];
    #pragma unroll
    for (int u = 0; u < 16; u++) hs[u] = b1[(size_t)e * DF + f0 + u];
    for (int k = 0; k < DM; k++) {
        float xk = xr[k];
        const float* wr = w1 + (size_t)k * DF + f0;
        #pragma unroll
        for (int u = 0; u < 16; u++) hs[u] += xk * wr[u];
    }
    float accs = 0.f;
    #pragma unroll
    for (int u = 0; u < 16; u++) accs += gelu_tanh(hs[u]) * w2[(size_t)(f0 + u) * DM + n];
    red[tid] = accs;
    __syncthreads();
    for (int st = 128; st > 0; st >>= 1) { if (tid < st) red[tid] += red[tid + st]; __syncthreads(); }
    if (tid == 0) {
        float ref = red[0] + b2[(size_t)e * DM + n];
        float got = out[(size_t)t * DM + n];
        if (fabsf(got - ref) > 0.05f + 0.02f * fabsf(ref)) g_ok = 0;
    }
}

// =================== FALLBACK: proven FFMA GEMMs (6.9ms) =====================
__global__ __launch_bounds__(256, 2) void k_gemm1(
    const float* __restrict__ X, const float* __restrict__ W1,
    const float* __restrict__ b1)
{
    if (g_ok) return;
    int e = blockIdx.z, cnt = g_cnt[e], m0 = blockIdx.x * 128;
    if (m0 >= cnt) return;
    int off = g_off[e], n0 = blockIdx.y * 128;
    const float* B = W1 + (size_t)e * DM * DF;
    __shared__ float As[8][128];
    __shared__ float Bs[8][128];
    int tid = threadIdx.x, tx = tid & 15, ty = tid >> 4;
    int am = tid >> 1, akq = (tid & 1) * 4, mg = m0 + am;
    const float* arow = (mg < cnt) ? (X + (size_t)g_list[off + mg] * DM) : nullptr;
    int bk = tid >> 5, bn = (tid & 31) * 4;
    float acc[8][8];
    #pragma unroll
    for (int i = 0; i < 8; i++)
        #pragma unroll
        for (int j = 0; j < 8; j++) acc[i][j] = 0.f;
    for (int k0 = 0; k0 < DM; k0 += 8) {
        float4 av = make_float4(0.f, 0.f, 0.f, 0.f);
        if (arow) av = *(const float4*)(arow + k0 + akq);
        float4 bv = *(const float4*)(B + (size_t)(k0 + bk) * DF + n0 + bn);
        As[akq + 0][am] = av.x; As[akq + 1][am] = av.y;
        As[akq + 2][am] = av.z; As[akq + 3][am] = av.w;
        *(float4*)&Bs[bk][bn] = bv;
        __syncthreads();
        #pragma unroll
        for (int kk = 0; kk < 8; kk++) {
            float a[8], b[8];
            #pragma unroll
            for (int i = 0; i < 8; i++) a[i] = As[kk][ty * 8 + i];
            #pragma unroll
            for (int j = 0; j < 8; j++) b[j] = Bs[kk][tx * 8 + j];
            #pragma unroll
            for (int i = 0; i < 8; i++)
                #pragma unroll
                for (int j = 0; j < 8; j++) acc[i][j] += a[i] * b[j];
        }
        __syncthreads();
    }
    const float* bb = b1 + (size_t)e * DF + n0 + tx * 8;
    float4 b1lo = *(const float4*)(bb);
    float4 b1hi = *(const float4*)(bb + 4);
    #pragma unroll
    for (int i = 0; i < 8; i++) {
        int m = m0 + ty * 8 + i;
        if (m < cnt) {
            float* hrow = g_h + (size_t)(off + m) * DF + n0 + tx * 8;
            float4 v0, v1;
            v0.x = gelu_tanh(acc[i][0] + b1lo.x); v0.y = gelu_tanh(acc[i][1] + b1lo.y);
            v0.z = gelu_tanh(acc[i][2] + b1lo.z); v0.w = gelu_tanh(acc[i][3] + b1lo.w);
            v1.x = gelu_tanh(acc[i][4] + b1hi.x); v1.y = gelu_tanh(acc[i][5] + b1hi.y);
            v1.z = gelu_tanh(acc[i][6] + b1hi.z); v1.w = gelu_tanh(acc[i][7] + b1hi.w);
            *(float4*)(hrow) = v0; *(float4*)(hrow + 4) = v1;
        }
    }
}

__global__ __launch_bounds__(256, 2) void k_gemm2(
    const float* __restrict__ W2, const float* __restrict__ b2,
    float* __restrict__ out)
{
    if (g_ok) return;
    int e = blockIdx.z, cnt = g_cnt[e], m0 = blockIdx.x * 128;
    if (m0 >= cnt) return;
    int off = g_off[e], n0 = blockIdx.y * 128;
    const float* B = W2 + (size_t)e * DF * DM;
    __shared__ float As[8][128];
    __shared__ float Bs[8][128];
    int tid = threadIdx.x, tx = tid & 15, ty = tid >> 4;
    int am = tid >> 1, akq = (tid & 1) * 4, mg = m0 + am;
    const float* arow = (mg < cnt) ? (g_h + (size_t)(off + mg) * DF) : nullptr;
    int bk = tid >> 5, bn = (tid & 31) * 4;
    float acc[8][8];
    #pragma unroll
    for (int i = 0; i < 8; i++)
        #pragma unroll
        for (int j = 0; j < 8; j++) acc[i][j] = 0.f;
    for (int k0 = 0; k0 < DF; k0 += 8) {
        float4 av = make_float4(0.f, 0.f, 0.f, 0.f);
        if (arow) av = *(const float4*)(arow + k0 + akq);
        float4 bv = *(const float4*)(B + (size_t)(k0 + bk) * DM + n0 + bn);
        As[akq + 0][am] = av.x; As[akq + 1][am] = av.y;
        As[akq + 2][am] = av.z; As[akq + 3][am] = av.w;
        *(float4*)&Bs[bk][bn] = bv;
        __syncthreads();
        #pragma unroll
        for (int kk = 0; kk < 8; kk++) {
            float a[8], b[8];
            #pragma unroll
            for (int i = 0; i < 8; i++) a[i] = As[kk][ty * 8 + i];
            #pragma unroll
            for (int j = 0; j < 8; j++) b[j] = Bs[kk][tx * 8 + j];
            #pragma unroll
            for (int i = 0; i < 8; i++)
                #pragma unroll
                for (int j = 0; j < 8; j++) acc[i][j] += a[i] * b[j];
        }
        __syncthreads();
    }
    const float* bb = b2 + (size_t)e * DM + n0 + tx * 8;
    float4 b2lo = *(const float4*)(bb);
    float4 b2hi = *(const float4*)(bb + 4);
    #pragma unroll
    for (int i = 0; i < 8; i++) {
        int m = m0 + ty * 8 + i;
        if (m < cnt) {
            int tok = g_list[off + m];
            float* orow = out + (size_t)tok * DM + n0 + tx * 8;
            float4 v0, v1;
            v0.x = acc[i][0] + b2lo.x; v0.y = acc[i][1] + b2lo.y;
            v0.z = acc[i][2] + b2lo.z; v0.w = acc[i][3] + b2lo.w;
            v1.x = acc[i][4] + b2hi.x; v1.y = acc[i][5] + b2hi.y;
            v1.z = acc[i][6] + b2hi.z; v1.w = acc[i][7] + b2hi.w;
            *(float4*)(orow) = v0; *(float4*)(orow + 4) = v1;
        }
    }
}

// -------------------------------- launch -------------------------------------
extern "C" void kernel_launch(void* const* d_in, const int* in_sizes, int n_in,
                              void* d_out, int out_size)
{
    const float* X   = (const float*)d_in[0];
    const int*   idx = (const int*)d_in[1];
    const float* W1  = (const float*)d_in[2];
    const float* b1  = (const float*)d_in[3];
    const float* W2  = (const float*)d_in[4];
    const float* b2  = (const float*)d_in[5];
    float*       out = (float*)d_out;
    (void)in_sizes; (void)n_in; (void)out_size;

    k_route0<<<1, 32>>>();
    k_route1<<<(NTOK + 255) / 256, 256>>>(idx);
    k_route2<<<1, 32>>>();
    k_route3<<<(NTOK + 255) / 256, 256>>>(idx);

    k_probe<<<1, 32>>>(X, W1);

    k_mma<0><<<dim3((NTOK / 128) * (DF / 128), 1, NE), 256>>>(X, W1, b1, out);
    k_mma<1><<<dim3((NTOK / 128) * (DM / 128), 1, NE), 256>>>(X, W2, b2, out);

    k_check<<<8, 256>>>(X, idx, W1, b1, W2, b2, out);

    k_gemm1<<<dim3(NTOK / 128, DF / 128, NE), 256>>>(X, W1, b1);
    k_gemm2<<<dim3(NTOK / 128, DM / 128, NE), 256>>>(W2, b2, out);
}